// round 5
// baseline (speedup 1.0000x reference)
#include <cuda_runtime.h>
#include <cuda_fp16.h>

#define D 128
#define MAX_DRUG 10000
#define MAX_DIS  15000
#define MAX_E    1048576
#define KC 16            // k-chunk per smem stage (proj)
#define NB 640           // row buckets, 16 rows each (covers 10240 rows)
#define HB 256           // histogram blocks fused behind proj

// Projected embeddings in fp16 (fp32 math, rounded once).
__device__ __half g_Ah[MAX_DRUG * D];   // z_drug    @ W1[0:128]  + b1
__device__ __half g_Bh[MAX_DIS  * D];   // z_disease @ W1[128:256]
// Bucketing scratch. g_cnt is zero at module load and re-zeroed by the
// scan kernel every launch, so each graph replay sees zeros.
__device__ int  g_cnt[NB];
__device__ int  g_ptr[NB + 1];
__device__ int  g_off[NB];
__device__ int2 g_rec[MAX_E];   // (col | r_local<<28, eid), bucket-grouped

// ---------------------------------------------------------------------------
// K1: fused projection GEMMs + edge-row histogram.
// Blocks [0, tiles): 128x128 output tile of A or B projection.
// Blocks [tiles, tiles+HB): smem-privatized histogram of row[e]>>4.
// ---------------------------------------------------------------------------
__global__ __launch_bounds__(256) void proj_hist_kernel(
    const float* __restrict__ Zd, const float* __restrict__ Zs_,
    int n_drug, int n_dis,
    const float* __restrict__ W1, const float* __restrict__ b1,
    __half* __restrict__ A, __half* __restrict__ B,
    const int* __restrict__ row, int E, int tiles, int do_hist)
{
    const int t = threadIdx.x;

    if ((int)blockIdx.x >= tiles) {                 // ---- histogram blocks
        if (!do_hist) return;
        __shared__ int hc[NB];
        const int hb = blockIdx.x - tiles;
        for (int i = t; i < NB; i += 256) hc[i] = 0;
        __syncthreads();
        for (int e = hb * 256 + t; e < E; e += 256 * HB)
            atomicAdd(&hc[row[e] >> 4], 1);
        __syncthreads();
        for (int i = t; i < NB; i += 256)
            if (hc[i]) atomicAdd(&g_cnt[i], hc[i]);
        return;
    }

    // ---- projection blocks
    const int tiles_drug = (n_drug + 127) / 128;
    const float* Z;
    __half* out;
    int N, koff, addb;
    int tile = blockIdx.x;
    if (tile < tiles_drug) { Z = Zd;  out = A; N = n_drug; koff = 0;   addb = 1; }
    else { tile -= tiles_drug; Z = Zs_; out = B; N = n_dis; koff = 128; addb = 0; }
    const int r0 = tile * 128;

    __shared__ float Zt[KC][128];   // k-major (transposed Z tile)
    __shared__ float Wt[KC][128];

    const int tx = t & 15;          // col group: cols tx*8 .. tx*8+7
    const int ty = t >> 4;          // row group: rows ty*8 .. ty*8+7

    float acc[8][8];
#pragma unroll
    for (int i = 0; i < 8; i++)
#pragma unroll
        for (int j = 0; j < 8; j++) acc[i][j] = 0.f;

    for (int kc = 0; kc < D; kc += KC) {
        __syncthreads();
#pragma unroll
        for (int i = t; i < 512; i += 256) {
            int rr = i & 127;
            int k4 = i >> 7;
            float4 v = make_float4(0.f, 0.f, 0.f, 0.f);
            if (r0 + rr < N)
                v = *reinterpret_cast<const float4*>(
                        Z + (size_t)(r0 + rr) * D + kc + k4 * 4);
            Zt[k4 * 4 + 0][rr] = v.x;
            Zt[k4 * 4 + 1][rr] = v.y;
            Zt[k4 * 4 + 2][rr] = v.z;
            Zt[k4 * 4 + 3][rr] = v.w;
        }
#pragma unroll
        for (int i = t; i < 512; i += 256) {
            int kk = i >> 5;
            int c4 = i & 31;
            *reinterpret_cast<float4*>(&Wt[kk][c4 * 4]) =
                *reinterpret_cast<const float4*>(
                    W1 + (size_t)(koff + kc + kk) * D + c4 * 4);
        }
        __syncthreads();

#pragma unroll
        for (int kk = 0; kk < KC; kk++) {
            float af[8], bf[8];
            *reinterpret_cast<float4*>(af)     = *reinterpret_cast<float4*>(&Zt[kk][ty * 8]);
            *reinterpret_cast<float4*>(af + 4) = *reinterpret_cast<float4*>(&Zt[kk][ty * 8 + 4]);
            *reinterpret_cast<float4*>(bf)     = *reinterpret_cast<float4*>(&Wt[kk][tx * 8]);
            *reinterpret_cast<float4*>(bf + 4) = *reinterpret_cast<float4*>(&Wt[kk][tx * 8 + 4]);
#pragma unroll
            for (int i = 0; i < 8; i++)
#pragma unroll
                for (int j = 0; j < 8; j++)
                    acc[i][j] = fmaf(af[i], bf[j], acc[i][j]);
        }
    }

    float bias[8];
#pragma unroll
    for (int j = 0; j < 8; j++) bias[j] = addb ? b1[tx * 8 + j] : 0.f;

#pragma unroll
    for (int i = 0; i < 8; i++) {
        int r = r0 + ty * 8 + i;
        if (r < N) {
            __half2 h[4];
#pragma unroll
            for (int j = 0; j < 4; j++)
                h[j] = __floats2half2_rn(acc[i][2 * j]     + bias[2 * j],
                                         acc[i][2 * j + 1] + bias[2 * j + 1]);
            *reinterpret_cast<uint4*>(out + (size_t)r * D + tx * 8) =
                *reinterpret_cast<uint4*>(h);
        }
    }
}

// ---------------------------------------------------------------------------
// K2: exclusive scan of 640 bucket counts (one block). Also resets g_cnt
// so the next graph replay starts from zeros.
// ---------------------------------------------------------------------------
__global__ __launch_bounds__(1024) void scan_kernel(int E)
{
    __shared__ int sA[1024], sB[1024];
    const int t = threadIdx.x;
    const int v = (t < NB) ? g_cnt[t] : 0;
    sA[t] = v;
    __syncthreads();

    int* src = sA;
    int* dst = sB;
#pragma unroll
    for (int off = 1; off < 1024; off <<= 1) {
        int x = src[t];
        if (t >= off) x += src[t - off];
        dst[t] = x;
        __syncthreads();
        int* tmp = src; src = dst; dst = tmp;
    }
    const int incl = src[t];

    if (t < NB) {
        g_ptr[t] = incl - v;
        g_off[t] = incl - v;
        g_cnt[t] = 0;          // re-arm for next replay
    }
    if (t == 1023) g_ptr[NB] = incl;   // == E
}

// ---------------------------------------------------------------------------
// K3: scatter edges into bucket-grouped records.
// ---------------------------------------------------------------------------
__global__ __launch_bounds__(256) void scatter_kernel(
    const int* __restrict__ row, const int* __restrict__ col, int E)
{
    for (int e = blockIdx.x * 256 + threadIdx.x; e < E;
         e += gridDim.x * 256) {
        const int r = row[e];
        const int c = col[e];
        const int p = atomicAdd(&g_off[r >> 4], 1);
        g_rec[p] = make_int2(c | ((r & 15) << 28), e);
    }
}

// ---------------------------------------------------------------------------
// K4: bucketed edge kernel. One block per bucket; its 16 A-rows live in
// smem, so only B is gathered through L2. 8 edges per warp as 4 pairs:
// lanes 0-15 = even edge, 16-31 = odd edge; one LDG.128 fetches both rows.
// ---------------------------------------------------------------------------
__global__ __launch_bounds__(256, 4) void edge_sorted_kernel(
    const float* __restrict__ W2, const float* __restrict__ b2,
    float* __restrict__ out, int n_drug)
{
    __shared__ uint4 As4[16 * 16];   // 16 rows x 256B = 4KB fp16

    const int t = threadIdx.x;
    const int b = blockIdx.x;

    // Stage this bucket's A rows (zero-pad rows beyond n_drug).
    {
        const uint4* A16 = reinterpret_cast<const uint4*>(g_Ah);
        const int r = b * 16 + (t >> 4);
        As4[t] = (r < n_drug) ? A16[r * 16 + (t & 15)]
                              : make_uint4(0u, 0u, 0u, 0u);
    }
    __syncthreads();

    const int seg0 = g_ptr[b];
    const int seg1 = g_ptr[b + 1];
    if (seg0 >= seg1) return;

    const int lane = t & 31;
    const int wid  = t >> 5;         // 0..7
    const int j    = lane & 15;      // 16B chunk within a 256B row
    const int hi   = lane >> 4;      // 0 = even edge of pair, 1 = odd

    // W2 features [j*8, j*8+8) as 4 half2.
    const float4 wa = reinterpret_cast<const float4*>(W2)[j * 2];
    const float4 wb = reinterpret_cast<const float4*>(W2)[j * 2 + 1];
    const __half2 w0  = __floats2half2_rn(wa.x, wa.y);
    const __half2 w1  = __floats2half2_rn(wa.z, wa.w);
    const __half2 w2h = __floats2half2_rn(wb.x, wb.y);
    const __half2 w3  = __floats2half2_rn(wb.z, wb.w);
    const float bias = b2[0];
    const __half2 zero = __float2half2_rn(0.f);
    const uint4* __restrict__ B16 = reinterpret_cast<const uint4*>(g_Bh);
    const unsigned full = 0xffffffffu;

    auto pair_dot = [&](const uint4& a, const uint4& bv) -> float {
        __half2 h0 = __hmax2(__hadd2(*reinterpret_cast<const __half2*>(&a.x),
                                     *reinterpret_cast<const __half2*>(&bv.x)), zero);
        __half2 h1 = __hmax2(__hadd2(*reinterpret_cast<const __half2*>(&a.y),
                                     *reinterpret_cast<const __half2*>(&bv.y)), zero);
        __half2 h2 = __hmax2(__hadd2(*reinterpret_cast<const __half2*>(&a.z),
                                     *reinterpret_cast<const __half2*>(&bv.z)), zero);
        __half2 h3 = __hmax2(__hadd2(*reinterpret_cast<const __half2*>(&a.w),
                                     *reinterpret_cast<const __half2*>(&bv.w)), zero);
        __half2 acc0 = __hfma2(h1, w1, __hmul2(h0, w0));
        __half2 acc1 = __hfma2(h3, w3, __hmul2(h2, w2h));
        float2 f0 = __half22float2(acc0);
        float2 f1 = __half22float2(acc1);
        return (f0.x + f0.y) + (f1.x + f1.y);
    };

    for (int base = seg0 + wid * 8; base < seg1; base += 64) {
        const int n = min(8, seg1 - base);

        int2 rec = make_int2(0, 0);
        if (lane < 8)
            rec = g_rec[min(base + lane, seg1 - 1)];

        // Broadcast pair records: pair p takes record 2p (low half) or
        // 2p+1 (high half).
        int rx[4], re[4];
#pragma unroll
        for (int p = 0; p < 4; p++) {
            rx[p] = __shfl_sync(full, rec.x, 2 * p + hi);
            re[p] = __shfl_sync(full, rec.y, 2 * p + hi);
        }

        // Front-batched loads: A from smem, B from gmem (4 LDG.128).
        uint4 av[4], bv[4];
#pragma unroll
        for (int p = 0; p < 4; p++) {
            const int c  = rx[p] & 0x0FFFFFFF;
            const int rl = ((unsigned)rx[p]) >> 28;
            av[p] = As4[rl * 16 + j];
            bv[p] = B16[(size_t)c * 16 + j];
        }

        float s[4];
#pragma unroll
        for (int p = 0; p < 4; p++) s[p] = pair_dot(av[p], bv[p]);

        // Butterfly within 16-lane halves.
#pragma unroll
        for (int off = 8; off > 0; off >>= 1) {
#pragma unroll
            for (int p = 0; p < 4; p++)
                s[p] += __shfl_xor_sync(full, s[p], off);
        }

        if (j == 0) {   // lanes 0 and 16
#pragma unroll
            for (int p = 0; p < 4; p++)
                if (2 * p + hi < n) out[re[p]] = s[p] + bias;
        }
    }
}

// ---------------------------------------------------------------------------
// Fallback edge kernel (round-4 style, unsorted) for out-of-capacity shapes.
// ---------------------------------------------------------------------------
__global__ __launch_bounds__(256) void edge_kernel_flat(
    const int* __restrict__ row, const int* __restrict__ col,
    const float* __restrict__ W2, const float* __restrict__ b2,
    float* __restrict__ out, int E)
{
    const int lane = threadIdx.x & 31;
    const int warp = blockIdx.x * 8 + (threadIdx.x >> 5);
    const int e0 = warp * 4;
    if (e0 >= E) return;

    const float4 w2 = reinterpret_cast<const float4*>(W2)[lane];
    const float bias = b2[0];
    const int last = E - 1;

    const int r0i = row[e0];
    const int c0i = col[e0];
    const int r1i = row[min(e0 + 1, last)];
    const int c1i = col[min(e0 + 1, last)];
    const int r2i = row[min(e0 + 2, last)];
    const int c2i = col[min(e0 + 2, last)];
    const int r3i = row[min(e0 + 3, last)];
    const int c3i = col[min(e0 + 3, last)];

    const uint2* __restrict__ Ah = reinterpret_cast<const uint2*>(g_Ah);
    const uint2* __restrict__ Bh = reinterpret_cast<const uint2*>(g_Bh);
    const uint2 a0 = Ah[(size_t)r0i * 32 + lane];
    const uint2 b0 = Bh[(size_t)c0i * 32 + lane];
    const uint2 a1 = Ah[(size_t)r1i * 32 + lane];
    const uint2 b1v = Bh[(size_t)c1i * 32 + lane];
    const uint2 a2 = Ah[(size_t)r2i * 32 + lane];
    const uint2 b2v = Bh[(size_t)c2i * 32 + lane];
    const uint2 a3 = Ah[(size_t)r3i * 32 + lane];
    const uint2 b3v = Bh[(size_t)c3i * 32 + lane];

    const __half2 zero = __float2half2_rn(0.f);
    auto edge_dot = [&](uint2 a, uint2 b) -> float {
        __half2 al = *reinterpret_cast<__half2*>(&a.x);
        __half2 ah = *reinterpret_cast<__half2*>(&a.y);
        __half2 bl = *reinterpret_cast<__half2*>(&b.x);
        __half2 bh = *reinterpret_cast<__half2*>(&b.y);
        __half2 h0 = __hmax2(__hadd2(al, bl), zero);
        __half2 h1 = __hmax2(__hadd2(ah, bh), zero);
        float2 f0 = __half22float2(h0);
        float2 f1 = __half22float2(h1);
        return f0.x * w2.x + f0.y * w2.y + f1.x * w2.z + f1.y * w2.w;
    };

    float s0 = edge_dot(a0, b0);
    float s1 = edge_dot(a1, b1v);
    float s2 = edge_dot(a2, b2v);
    float s3 = edge_dot(a3, b3v);

    const unsigned full = 0xffffffffu;
    const bool hi = (lane & 16) != 0;
    float va = hi ? s1 : s0;
    float oa = hi ? s0 : s1;
    va += __shfl_xor_sync(full, oa, 16);
    float vb = hi ? s3 : s2;
    float ob = hi ? s2 : s3;
    vb += __shfl_xor_sync(full, ob, 16);
#pragma unroll
    for (int off = 8; off > 0; off >>= 1) {
        va += __shfl_xor_sync(full, va, off);
        vb += __shfl_xor_sync(full, vb, off);
    }
    if (lane == 0) {
        out[e0] = va + bias;
        if (e0 + 2 < E) out[e0 + 2] = vb + bias;
    } else if (lane == 16) {
        if (e0 + 1 < E) out[e0 + 1] = va + bias;
        if (e0 + 3 < E) out[e0 + 3] = vb + bias;
    }
}

extern "C" void kernel_launch(void* const* d_in, const int* in_sizes, int n_in,
                              void* d_out, int out_size)
{
    const float* z_drug = (const float*)d_in[0];
    const float* z_dis  = (const float*)d_in[1];
    const int*   row    = (const int*)  d_in[2];
    const int*   col    = (const int*)  d_in[3];
    const float* W1     = (const float*)d_in[4];
    const float* b1     = (const float*)d_in[5];
    const float* W2     = (const float*)d_in[6];
    const float* b2     = (const float*)d_in[7];
    float* out = (float*)d_out;

    const int n_drug = in_sizes[0] / D;
    const int n_dis  = in_sizes[1] / D;
    const int E      = in_sizes[2];

    __half *dA = nullptr, *dB = nullptr;
    cudaGetSymbolAddress((void**)&dA, g_Ah);
    cudaGetSymbolAddress((void**)&dB, g_Bh);

    const int tiles = (n_drug + 127) / 128 + (n_dis + 127) / 128;
    const bool bucketed = (E <= MAX_E) && (n_drug <= NB * 16);

    if (bucketed) {
        // K1: projections + histogram (hist hides behind the GEMM wave).
        proj_hist_kernel<<<tiles + HB, 256>>>(
            z_drug, z_dis, n_drug, n_dis, W1, b1, dA, dB, row, E, tiles, 1);
        // K2: bucket prefix-sum (+ counter re-arm for graph replay).
        scan_kernel<<<1, 1024>>>(E);
        // K3: bucket-grouped records.
        scatter_kernel<<<512, 256>>>(row, col, E);
        // K4: edge compute; A from smem, B gathered from L2.
        edge_sorted_kernel<<<NB, 256>>>(W2, b2, out, n_drug);
    } else {
        proj_hist_kernel<<<tiles, 256>>>(
            z_drug, z_dis, n_drug, n_dis, W1, b1, dA, dB, row, E, tiles, 0);
        const int warps  = (E + 3) / 4;
        const int blocks = (warps + 7) / 8;
        edge_kernel_flat<<<blocks, 256>>>(row, col, W2, b2, out, E);
    }
}

// round 6
// speedup vs baseline: 2.4061x; 2.4061x over previous
#include <cuda_runtime.h>
#include <cuda_fp16.h>

#define D 128
#define MAX_DRUG 10000
#define MAX_DIS  15000
#define MAX_E    1048576
#define KC 16            // k-chunk per smem stage (proj)
#define NB 640           // row buckets, 16 rows each (covers 10240 rows)
#define HB 256           // edge chunks (hist/scatter blocks)
#define SPLIT 4          // blocks per bucket in the edge kernel

// Projected embeddings in fp16 (fp32 math, rounded once).
__device__ __half g_Ah[MAX_DRUG * D];   // z_drug    @ W1[0:128]  + b1
__device__ __half g_Bh[MAX_DIS  * D];   // z_disease @ W1[128:256]
// Counting-sort scratch. g_cnt zero at load; re-zeroed by scan each launch.
__device__ int  g_cnt[NB];
__device__ int  g_ptr[NB + 1];
__device__ int  g_blkhist[HB * NB];   // per-chunk histograms (overwritten)
__device__ int  g_base[HB * NB];      // per-(chunk,bucket) scatter bases
__device__ int2 g_rec[MAX_E];         // (col | r_local<<28, eid)

// ---------------------------------------------------------------------------
// K1: fused projection GEMMs + per-chunk edge-row histograms.
// Blocks [0, tiles): 128x128 projection tiles. Blocks [tiles, tiles+HB):
// contiguous-chunk histograms (matching K4's chunking exactly).
// ---------------------------------------------------------------------------
__global__ __launch_bounds__(256) void proj_hist_kernel(
    const float* __restrict__ Zd, const float* __restrict__ Zs_,
    int n_drug, int n_dis,
    const float* __restrict__ W1, const float* __restrict__ b1,
    __half* __restrict__ A, __half* __restrict__ B,
    const int* __restrict__ row, int E, int tiles, int do_hist)
{
    const int t = threadIdx.x;

    if ((int)blockIdx.x >= tiles) {                 // ---- histogram blocks
        if (!do_hist) return;
        __shared__ int hc[NB];
        const int hb = blockIdx.x - tiles;
        const int cs = (E + HB - 1) / HB;
        const int e0 = hb * cs;
        const int e1 = min(e0 + cs, E);
        for (int i = t; i < NB; i += 256) hc[i] = 0;
        __syncthreads();
        for (int e = e0 + t; e < e1; e += 256)
            atomicAdd(&hc[row[e] >> 4], 1);
        __syncthreads();
        for (int i = t; i < NB; i += 256) {
            const int v = hc[i];
            g_blkhist[hb * NB + i] = v;            // full row write
            if (v) atomicAdd(&g_cnt[i], v);        // fire-and-forget RED
        }
        return;
    }

    // ---- projection blocks
    const int tiles_drug = (n_drug + 127) / 128;
    const float* Z;
    __half* out;
    int N, koff, addb;
    int tile = blockIdx.x;
    if (tile < tiles_drug) { Z = Zd;  out = A; N = n_drug; koff = 0;   addb = 1; }
    else { tile -= tiles_drug; Z = Zs_; out = B; N = n_dis; koff = 128; addb = 0; }
    const int r0 = tile * 128;

    __shared__ float Zt[KC][128];
    __shared__ float Wt[KC][128];

    const int tx = t & 15;
    const int ty = t >> 4;

    float acc[8][8];
#pragma unroll
    for (int i = 0; i < 8; i++)
#pragma unroll
        for (int j = 0; j < 8; j++) acc[i][j] = 0.f;

    for (int kc = 0; kc < D; kc += KC) {
        __syncthreads();
#pragma unroll
        for (int i = t; i < 512; i += 256) {
            int rr = i & 127;
            int k4 = i >> 7;
            float4 v = make_float4(0.f, 0.f, 0.f, 0.f);
            if (r0 + rr < N)
                v = *reinterpret_cast<const float4*>(
                        Z + (size_t)(r0 + rr) * D + kc + k4 * 4);
            Zt[k4 * 4 + 0][rr] = v.x;
            Zt[k4 * 4 + 1][rr] = v.y;
            Zt[k4 * 4 + 2][rr] = v.z;
            Zt[k4 * 4 + 3][rr] = v.w;
        }
#pragma unroll
        for (int i = t; i < 512; i += 256) {
            int kk = i >> 5;
            int c4 = i & 31;
            *reinterpret_cast<float4*>(&Wt[kk][c4 * 4]) =
                *reinterpret_cast<const float4*>(
                    W1 + (size_t)(koff + kc + kk) * D + c4 * 4);
        }
        __syncthreads();

#pragma unroll
        for (int kk = 0; kk < KC; kk++) {
            float af[8], bf[8];
            *reinterpret_cast<float4*>(af)     = *reinterpret_cast<float4*>(&Zt[kk][ty * 8]);
            *reinterpret_cast<float4*>(af + 4) = *reinterpret_cast<float4*>(&Zt[kk][ty * 8 + 4]);
            *reinterpret_cast<float4*>(bf)     = *reinterpret_cast<float4*>(&Wt[kk][tx * 8]);
            *reinterpret_cast<float4*>(bf + 4) = *reinterpret_cast<float4*>(&Wt[kk][tx * 8 + 4]);
#pragma unroll
            for (int i = 0; i < 8; i++)
#pragma unroll
                for (int j = 0; j < 8; j++)
                    acc[i][j] = fmaf(af[i], bf[j], acc[i][j]);
        }
    }

    float bias[8];
#pragma unroll
    for (int j = 0; j < 8; j++) bias[j] = addb ? b1[tx * 8 + j] : 0.f;

#pragma unroll
    for (int i = 0; i < 8; i++) {
        int r = r0 + ty * 8 + i;
        if (r < N) {
            __half2 h[4];
#pragma unroll
            for (int j = 0; j < 4; j++)
                h[j] = __floats2half2_rn(acc[i][2 * j]     + bias[2 * j],
                                         acc[i][2 * j + 1] + bias[2 * j + 1]);
            *reinterpret_cast<uint4*>(out + (size_t)r * D + tx * 8) =
                *reinterpret_cast<uint4*>(h);
        }
    }
}

// ---------------------------------------------------------------------------
// K2: exclusive scan of 640 bucket totals (1 block); re-arms g_cnt.
// ---------------------------------------------------------------------------
__global__ __launch_bounds__(1024) void scan_kernel(int E)
{
    __shared__ int sA[1024], sB[1024];
    const int t = threadIdx.x;
    const int v = (t < NB) ? g_cnt[t] : 0;
    sA[t] = v;
    __syncthreads();

    int* src = sA;
    int* dst = sB;
#pragma unroll
    for (int off = 1; off < 1024; off <<= 1) {
        int x = src[t];
        if (t >= off) x += src[t - off];
        dst[t] = x;
        __syncthreads();
        int* tmp = src; src = dst; dst = tmp;
    }
    const int incl = src[t];

    if (t < NB) {
        g_ptr[t] = incl - v;
        g_cnt[t] = 0;
    }
    if (t == 1023) g_ptr[NB] = incl;
}

// ---------------------------------------------------------------------------
// K3: per-bucket scan over 256 chunk counts -> atomic-free scatter bases.
// Block b: g_base[hb][b] = g_ptr[b] + sum_{h<hb} g_blkhist[h][b].
// ---------------------------------------------------------------------------
__global__ __launch_bounds__(256) void base_kernel()
{
    __shared__ int sA[256], sB[256];
    const int b = blockIdx.x;
    const int t = threadIdx.x;
    const int v = g_blkhist[t * NB + b];
    sA[t] = v;
    __syncthreads();

    int* src = sA;
    int* dst = sB;
#pragma unroll
    for (int off = 1; off < 256; off <<= 1) {
        int x = src[t];
        if (t >= off) x += src[t - off];
        dst[t] = x;
        __syncthreads();
        int* tmp = src; src = dst; dst = tmp;
    }
    g_base[t * NB + b] = g_ptr[b] + src[t] - v;   // exclusive
}

// ---------------------------------------------------------------------------
// K4: scatter — smem atomics only, against precomputed bases.
// ---------------------------------------------------------------------------
__global__ __launch_bounds__(256) void scatter_kernel(
    const int* __restrict__ row, const int* __restrict__ col, int E)
{
    __shared__ int soff[NB];
    const int hb = blockIdx.x;
    const int t  = threadIdx.x;
    const int cs = (E + HB - 1) / HB;
    const int e0 = hb * cs;
    const int e1 = min(e0 + cs, E);

    for (int i = t; i < NB; i += 256) soff[i] = g_base[hb * NB + i];
    __syncthreads();

    for (int e = e0 + t; e < e1; e += 256) {
        const int r = row[e];
        const int c = col[e];
        const int p = atomicAdd(&soff[r >> 4], 1);
        g_rec[p] = make_int2(c | ((r & 15) << 28), e);
    }
}

// ---------------------------------------------------------------------------
// K5: bucketed edge compute. SPLIT blocks per bucket (grid NB*SPLIT);
// each stages the bucket's 16 A-rows in smem (4KB) and processes a
// contiguous quarter of the segment. 8 edges/warp as 4 pairs.
// ---------------------------------------------------------------------------
__global__ __launch_bounds__(256) void edge_sorted_kernel(
    const float* __restrict__ W2, const float* __restrict__ b2,
    float* __restrict__ out, int n_drug)
{
    __shared__ uint4 As4[16 * 16];

    const int t    = threadIdx.x;
    const int b    = blockIdx.x >> 2;     // bucket
    const int part = blockIdx.x & 3;

    {
        const uint4* A16 = reinterpret_cast<const uint4*>(g_Ah);
        const int r = b * 16 + (t >> 4);
        As4[t] = (r < n_drug) ? A16[r * 16 + (t & 15)]
                              : make_uint4(0u, 0u, 0u, 0u);
    }
    __syncthreads();

    const int s0  = g_ptr[b];
    const int len = g_ptr[b + 1] - s0;
    const int q0  = s0 + (int)(((long long)len * part) / SPLIT);
    const int q1  = s0 + (int)(((long long)len * (part + 1)) / SPLIT);
    if (q0 >= q1) return;

    const int lane = t & 31;
    const int wid  = t >> 5;
    const int j    = lane & 15;
    const int hi   = lane >> 4;

    const float4 wa = reinterpret_cast<const float4*>(W2)[j * 2];
    const float4 wb = reinterpret_cast<const float4*>(W2)[j * 2 + 1];
    const __half2 w0  = __floats2half2_rn(wa.x, wa.y);
    const __half2 w1  = __floats2half2_rn(wa.z, wa.w);
    const __half2 w2h = __floats2half2_rn(wb.x, wb.y);
    const __half2 w3  = __floats2half2_rn(wb.z, wb.w);
    const float bias = b2[0];
    const __half2 zero = __float2half2_rn(0.f);
    const uint4* __restrict__ B16 = reinterpret_cast<const uint4*>(g_Bh);
    const unsigned full = 0xffffffffu;

    auto pair_dot = [&](const uint4& a, const uint4& bv) -> float {
        __half2 h0 = __hmax2(__hadd2(*reinterpret_cast<const __half2*>(&a.x),
                                     *reinterpret_cast<const __half2*>(&bv.x)), zero);
        __half2 h1 = __hmax2(__hadd2(*reinterpret_cast<const __half2*>(&a.y),
                                     *reinterpret_cast<const __half2*>(&bv.y)), zero);
        __half2 h2 = __hmax2(__hadd2(*reinterpret_cast<const __half2*>(&a.z),
                                     *reinterpret_cast<const __half2*>(&bv.z)), zero);
        __half2 h3 = __hmax2(__hadd2(*reinterpret_cast<const __half2*>(&a.w),
                                     *reinterpret_cast<const __half2*>(&bv.w)), zero);
        __half2 acc0 = __hfma2(h1, w1, __hmul2(h0, w0));
        __half2 acc1 = __hfma2(h3, w3, __hmul2(h2, w2h));
        float2 f0 = __half22float2(acc0);
        float2 f1 = __half22float2(acc1);
        return (f0.x + f0.y) + (f1.x + f1.y);
    };

    for (int base = q0 + wid * 8; base < q1; base += 64) {
        const int n = min(8, q1 - base);

        int2 rec = make_int2(0, 0);
        if (lane < 8)
            rec = g_rec[min(base + lane, q1 - 1)];

        int rx[4], re[4];
#pragma unroll
        for (int p = 0; p < 4; p++) {
            rx[p] = __shfl_sync(full, rec.x, 2 * p + hi);
            re[p] = __shfl_sync(full, rec.y, 2 * p + hi);
        }

        uint4 av[4], bv[4];
#pragma unroll
        for (int p = 0; p < 4; p++) {
            const int c  = rx[p] & 0x0FFFFFFF;
            const int rl = ((unsigned)rx[p]) >> 28;
            av[p] = As4[rl * 16 + j];
            bv[p] = B16[(size_t)c * 16 + j];
        }

        float s[4];
#pragma unroll
        for (int p = 0; p < 4; p++) s[p] = pair_dot(av[p], bv[p]);

#pragma unroll
        for (int off = 8; off > 0; off >>= 1) {
#pragma unroll
            for (int p = 0; p < 4; p++)
                s[p] += __shfl_xor_sync(full, s[p], off);
        }

        if (j == 0) {
#pragma unroll
            for (int p = 0; p < 4; p++)
                if (2 * p + hi < n) out[re[p]] = s[p] + bias;
        }
    }
}

// ---------------------------------------------------------------------------
// Fallback flat edge kernel (round-4, 49.7us known-good) for odd shapes.
// ---------------------------------------------------------------------------
__global__ __launch_bounds__(256) void edge_kernel_flat(
    const int* __restrict__ row, const int* __restrict__ col,
    const float* __restrict__ W2, const float* __restrict__ b2,
    float* __restrict__ out, int E)
{
    const int lane = threadIdx.x & 31;
    const int warp = blockIdx.x * 8 + (threadIdx.x >> 5);
    const int e0 = warp * 4;
    if (e0 >= E) return;

    const float4 w2 = reinterpret_cast<const float4*>(W2)[lane];
    const float bias = b2[0];
    const int last = E - 1;

    const int r0i = row[e0];
    const int c0i = col[e0];
    const int r1i = row[min(e0 + 1, last)];
    const int c1i = col[min(e0 + 1, last)];
    const int r2i = row[min(e0 + 2, last)];
    const int c2i = col[min(e0 + 2, last)];
    const int r3i = row[min(e0 + 3, last)];
    const int c3i = col[min(e0 + 3, last)];

    const uint2* __restrict__ Ah = reinterpret_cast<const uint2*>(g_Ah);
    const uint2* __restrict__ Bh = reinterpret_cast<const uint2*>(g_Bh);
    const uint2 a0 = Ah[(size_t)r0i * 32 + lane];
    const uint2 b0 = Bh[(size_t)c0i * 32 + lane];
    const uint2 a1 = Ah[(size_t)r1i * 32 + lane];
    const uint2 b1v = Bh[(size_t)c1i * 32 + lane];
    const uint2 a2 = Ah[(size_t)r2i * 32 + lane];
    const uint2 b2v = Bh[(size_t)c2i * 32 + lane];
    const uint2 a3 = Ah[(size_t)r3i * 32 + lane];
    const uint2 b3v = Bh[(size_t)c3i * 32 + lane];

    const __half2 zero = __float2half2_rn(0.f);
    auto edge_dot = [&](uint2 a, uint2 b) -> float {
        __half2 al = *reinterpret_cast<__half2*>(&a.x);
        __half2 ah = *reinterpret_cast<__half2*>(&a.y);
        __half2 bl = *reinterpret_cast<__half2*>(&b.x);
        __half2 bh = *reinterpret_cast<__half2*>(&b.y);
        __half2 h0 = __hmax2(__hadd2(al, bl), zero);
        __half2 h1 = __hmax2(__hadd2(ah, bh), zero);
        float2 f0 = __half22float2(h0);
        float2 f1 = __half22float2(h1);
        return f0.x * w2.x + f0.y * w2.y + f1.x * w2.z + f1.y * w2.w;
    };

    float s0 = edge_dot(a0, b0);
    float s1 = edge_dot(a1, b1v);
    float s2 = edge_dot(a2, b2v);
    float s3 = edge_dot(a3, b3v);

    const unsigned full = 0xffffffffu;
    const bool hi = (lane & 16) != 0;
    float va = hi ? s1 : s0;
    float oa = hi ? s0 : s1;
    va += __shfl_xor_sync(full, oa, 16);
    float vb = hi ? s3 : s2;
    float ob = hi ? s2 : s3;
    vb += __shfl_xor_sync(full, ob, 16);
#pragma unroll
    for (int off = 8; off > 0; off >>= 1) {
        va += __shfl_xor_sync(full, va, off);
        vb += __shfl_xor_sync(full, vb, off);
    }
    if (lane == 0) {
        out[e0] = va + bias;
        if (e0 + 2 < E) out[e0 + 2] = vb + bias;
    } else if (lane == 16) {
        if (e0 + 1 < E) out[e0 + 1] = va + bias;
        if (e0 + 3 < E) out[e0 + 3] = vb + bias;
    }
}

extern "C" void kernel_launch(void* const* d_in, const int* in_sizes, int n_in,
                              void* d_out, int out_size)
{
    const float* z_drug = (const float*)d_in[0];
    const float* z_dis  = (const float*)d_in[1];
    const int*   row    = (const int*)  d_in[2];
    const int*   col    = (const int*)  d_in[3];
    const float* W1     = (const float*)d_in[4];
    const float* b1     = (const float*)d_in[5];
    const float* W2     = (const float*)d_in[6];
    const float* b2     = (const float*)d_in[7];
    float* out = (float*)d_out;

    const int n_drug = in_sizes[0] / D;
    const int n_dis  = in_sizes[1] / D;
    const int E      = in_sizes[2];

    __half *dA = nullptr, *dB = nullptr;
    cudaGetSymbolAddress((void**)&dA, g_Ah);
    cudaGetSymbolAddress((void**)&dB, g_Bh);

    const int tiles = (n_drug + 127) / 128 + (n_dis + 127) / 128;
    const bool bucketed = (E <= MAX_E) && (n_drug <= NB * 16);

    if (bucketed) {
        proj_hist_kernel<<<tiles + HB, 256>>>(
            z_drug, z_dis, n_drug, n_dis, W1, b1, dA, dB, row, E, tiles, 1);
        scan_kernel<<<1, 1024>>>(E);
        base_kernel<<<NB, 256>>>();
        scatter_kernel<<<HB, 256>>>(row, col, E);
        edge_sorted_kernel<<<NB * SPLIT, 256>>>(W2, b2, out, n_drug);
    } else {
        proj_hist_kernel<<<tiles, 256>>>(
            z_drug, z_dis, n_drug, n_dis, W1, b1, dA, dB, row, E, tiles, 0);
        const int warps  = (E + 3) / 4;
        const int blocks = (warps + 7) / 8;
        edge_kernel_flat<<<blocks, 256>>>(row, col, W2, b2, out, E);
    }
}